// round 14
// baseline (speedup 1.0000x reference)
#include <cuda_runtime.h>
#include <cstdint>

// AdjustableModePooling — R14: R12 core + 512-thread/16-row CTAs (last config probe).
//   x: (64, 65536, 10) f32 of integer labels 0..9, flat-viewed as (B=64, C=10, D=65536)
//   window K1=8 along D, mode per window (ties -> smallest value)
//   out flat index = c*(8192*64) + j*64 + b
//
// Core design (evidence-backed, unchanged from R12 best: 33.248us):
//  - LDG.256: lane l loads window l whole, warp covers 1024B coalesced
//  - nibble histogram via fma(f,4,2^23); byte-packed key argmax; exponent-magic cast
// New in R14: block=512 (16 warps = 16 b-rows), grid 5120; store phase writes
// 64B-contiguous segments per warp; smem transpose stride 17 (odd -> conflict-free).

static constexpr unsigned B  = 64;
static constexpr unsigned C  = 10;
static constexpr unsigned D  = 65536;
static constexpr unsigned NJ = 8192;     // (D-8)/8+1
static constexpr unsigned JT = 64;       // windows per block tile (per row)
static constexpr unsigned RT = 16;       // rows (b values) per block = warps per block

__device__ __forceinline__ unsigned kmax(unsigned a, unsigned b) { return a > b ? a : b; }

struct F8 { float a,b,c,d,e,f,g,h; };

__device__ __forceinline__ F8 ldg256(const float* p)
{
    F8 r;
    asm volatile("ld.global.nc.v8.f32 {%0,%1,%2,%3,%4,%5,%6,%7}, [%8];"
                 : "=f"(r.a), "=f"(r.b), "=f"(r.c), "=f"(r.d),
                   "=f"(r.e), "=f"(r.f), "=f"(r.g), "=f"(r.h)
                 : "l"(p));
    return r;
}

__device__ __forceinline__ unsigned long long hist4(float a, float b_, float c_, float d_)
{
    // fma(f,4,2^23): bits = 0x4B000000 | 4v (exact for v in 0..9); bits&63 == 4v
    unsigned long long h = 0ull;
    h += 1ull << (__float_as_uint(__fmaf_rn(a,  4.0f, 8388608.0f)) & 63u);
    h += 1ull << (__float_as_uint(__fmaf_rn(b_, 4.0f, 8388608.0f)) & 63u);
    h += 1ull << (__float_as_uint(__fmaf_rn(c_, 4.0f, 8388608.0f)) & 63u);
    h += 1ull << (__float_as_uint(__fmaf_rn(d_, 4.0f, 8388608.0f)) & 63u);
    return h;
}

__device__ __forceinline__ float window_mode(const F8& v)
{
    unsigned long long acc = hist4(v.a, v.b, v.c, v.d)
                           + hist4(v.e, v.f, v.g, v.h);
    unsigned lo = (unsigned)acc;          // counts of v=0..7, nibble v
    unsigned hi = (unsigned)(acc >> 32);  // counts of v=8 (nib0), v=9 (nib1)

    // key_v = (count_v << 4) | (15 - v); max key wins; tie -> smallest v.
    unsigned E = ((lo << 4) & 0xF0F0F0F0u) | 0x090B0D0Fu;  // bytes: v=0,2,4,6
    unsigned O = ( lo       & 0xF0F0F0F0u) | 0x080A0C0Eu;  // bytes: v=1,3,5,7

    unsigned M = __vmaxu4(E, O);
    M = __vmaxu4(M, M >> 16);
    M = __vmaxu4(M, M >> 8);              // byte0 = max of the 8 low-bin keys

    unsigned k8 = ((hi << 4) & 0xF0u) | 7u;
    unsigned k9 = ( hi       & 0xF0u) | 6u;
    unsigned best = kmax(M & 0xFFu, kmax(k8, k9));

    // mode = 15 - (best & 15) = (~best) & 15 ; int->float via exponent magic
    unsigned r = (~best) & 15u;
    return __uint_as_float(0x4B000000u | r) - 8388608.0f;
}

__global__ __launch_bounds__(512, 3)
void mode_pool_kernel(const float* __restrict__ x, float* __restrict__ out)
{
    __shared__ float s_out[JT * 17];         // [j_local][row], stride 17 (odd) -> conflict-free

    unsigned g  = blockIdx.x;
    unsigned jt = g & 127u;                  // 128 j-tiles of 64 windows
    unsigned bg = (g >> 7) & 3u;             // 4 groups of 16 b-rows
    unsigned c  = g >> 9;                    // 0..9

    unsigned t = threadIdx.x;
    unsigned w = t >> 5;                     // warp -> row within group (0..15)
    unsigned l = t & 31u;                    // lane -> window within 32-window chunk
    unsigned b = bg * RT + w;

    const float* rp = x + (size_t)b * (C * D) + (size_t)c * D + (size_t)jt * (JT * 8u);

    // 2 chunks of 32 windows; lane l owns window l of each chunk, loaded whole
    // as one LDG.256 (warp covers 1024B contiguous, fully coalesced).
    F8 v0 = ldg256(rp + 8u * l);
    F8 v1 = ldg256(rp + 256u + 8u * l);

    s_out[l * 17u + w]         = window_mode(v0);   // banks (17l + w) % 32: permutation in l
    s_out[(32u + l) * 17u + w] = window_mode(v1);
    __syncthreads();

    // Store phase: thread t -> (j = t>>4 (+32r), b_off = t&15). Each warp writes
    // two 64B-contiguous segments per round (bg*16 floats = 64B aligned).
    float* ob = out + (size_t)c * (NJ * B) + (size_t)(jt * JT) * B + (size_t)bg * RT;
    unsigned bo = t & 15u;
    unsigned j0 = t >> 4;                    // 0..31
#pragma unroll
    for (int r = 0; r < 2; r++) {
        unsigned j = j0 + 32u * r;
        __stcs(&ob[(size_t)j * B + bo], s_out[j * 17u + bo]);
    }
}

extern "C" void kernel_launch(void* const* d_in, const int* in_sizes, int n_in,
                              void* d_out, int out_size)
{
    const float* x = (const float*)d_in[0];
    float* out = (float*)d_out;
    // blocks = 128 j-tiles * 4 b-groups * 10 c = 5120, 512 threads each
    mode_pool_kernel<<<5120, 512>>>(x, out);
}

// round 15
// speedup vs baseline: 1.0077x; 1.0077x over previous
#include <cuda_runtime.h>
#include <cstdint>

// AdjustableModePooling — FINAL (R12 configuration; best measured 33.248us wall,
// device 30.43us, DRAM 74.9% / 5.93 TB/s, L1 28%, rel_err 0.0; reproduced 3x).
//
//   x: (64, 65536, 10) f32 of integer labels 0..9, flat-viewed as (B=64, C=10, D=65536)
//   window K1=8 along D, mode per window (ties -> smallest value)
//   out flat index = c*(8192*64) + j*64 + b
//
// Design (each element evidence-backed across 14 rounds):
//  - LDG.256 (Blackwell ld.global.nc.v8.f32): lane l loads window l WHOLE while
//    the warp covers 1024B fully coalesced (halves LDG count; L1 41->28%)
//  - lane = window along D (R3: the decisive win, -24% dur vs b-strided lanes)
//  - smem transpose (stride-9, conflict-free) -> stores 32B-full-sector coalesced
//  - nibble histogram in a u64 via fma(f,4,2^23): bits&63 == 4v, no F2I
//  - key argmax (cnt<<4)|(15-v), byte-packed + __vmaxu4 fold; tie -> smallest value
//  - int->float result via exponent-magic FADD, no I2F
//  - __stcs streaming stores (zero-reuse output)
// Measured-neutral/negative and rejected: occupancy boost (R4), cp.async pipeline
// (R6, -43%), persistent CTAs (R7, -7%), STG.64 (R8), shfl-butterfly loads (R9),
// 512-thread CTAs (R14). Kernel sits at the byte floor x achievable HBM sustain
// (~180MB mandatory traffic at ~5.9 TB/s) for this streaming access mix.

static constexpr unsigned B  = 64;
static constexpr unsigned C  = 10;
static constexpr unsigned D  = 65536;
static constexpr unsigned NJ = 8192;     // (D-8)/8+1
static constexpr unsigned JT = 64;       // windows per block tile (per row)
static constexpr unsigned RT = 8;        // rows (b values) per block = warps per block

__device__ __forceinline__ unsigned kmax(unsigned a, unsigned b) { return a > b ? a : b; }

struct F8 { float a,b,c,d,e,f,g,h; };

__device__ __forceinline__ F8 ldg256(const float* p)
{
    F8 r;
    asm volatile("ld.global.nc.v8.f32 {%0,%1,%2,%3,%4,%5,%6,%7}, [%8];"
                 : "=f"(r.a), "=f"(r.b), "=f"(r.c), "=f"(r.d),
                   "=f"(r.e), "=f"(r.f), "=f"(r.g), "=f"(r.h)
                 : "l"(p));
    return r;
}

__device__ __forceinline__ unsigned long long hist4(float a, float b_, float c_, float d_)
{
    // fma(f,4,2^23): bits = 0x4B000000 | 4v (exact for v in 0..9); bits&63 == 4v
    unsigned long long h = 0ull;
    h += 1ull << (__float_as_uint(__fmaf_rn(a,  4.0f, 8388608.0f)) & 63u);
    h += 1ull << (__float_as_uint(__fmaf_rn(b_, 4.0f, 8388608.0f)) & 63u);
    h += 1ull << (__float_as_uint(__fmaf_rn(c_, 4.0f, 8388608.0f)) & 63u);
    h += 1ull << (__float_as_uint(__fmaf_rn(d_, 4.0f, 8388608.0f)) & 63u);
    return h;
}

__device__ __forceinline__ float window_mode(const F8& v)
{
    unsigned long long acc = hist4(v.a, v.b, v.c, v.d)
                           + hist4(v.e, v.f, v.g, v.h);
    unsigned lo = (unsigned)acc;          // counts of v=0..7, nibble v
    unsigned hi = (unsigned)(acc >> 32);  // counts of v=8 (nib0), v=9 (nib1)

    // key_v = (count_v << 4) | (15 - v); max key wins; tie -> smallest v.
    unsigned E = ((lo << 4) & 0xF0F0F0F0u) | 0x090B0D0Fu;  // bytes: v=0,2,4,6
    unsigned O = ( lo       & 0xF0F0F0F0u) | 0x080A0C0Eu;  // bytes: v=1,3,5,7

    unsigned M = __vmaxu4(E, O);
    M = __vmaxu4(M, M >> 16);
    M = __vmaxu4(M, M >> 8);              // byte0 = max of the 8 low-bin keys

    unsigned k8 = ((hi << 4) & 0xF0u) | 7u;
    unsigned k9 = ( hi       & 0xF0u) | 6u;
    unsigned best = kmax(M & 0xFFu, kmax(k8, k9));

    // mode = 15 - (best & 15) = (~best) & 15 ; int->float via exponent magic
    unsigned r = (~best) & 15u;
    return __uint_as_float(0x4B000000u | r) - 8388608.0f;
}

__global__ __launch_bounds__(256, 7)
void mode_pool_kernel(const float* __restrict__ x, float* __restrict__ out)
{
    __shared__ float s_out[JT * 9];          // [j_local][row], stride 9 -> no bank conflicts

    unsigned g  = blockIdx.x;
    unsigned jt = g & 127u;                  // 128 j-tiles of 64 windows
    unsigned bg = (g >> 7) & 7u;             // 8 groups of 8 b-rows
    unsigned c  = g >> 10;                   // 0..9

    unsigned w = threadIdx.x >> 5;           // warp -> row within group
    unsigned l = threadIdx.x & 31u;          // lane -> window within 32-window chunk
    unsigned b = bg * RT + w;

    const float* rp = x + (size_t)b * (C * D) + (size_t)c * D + (size_t)jt * (JT * 8u);

    // 2 chunks of 32 windows; lane l owns window l of each chunk, loaded whole
    // as one LDG.256 (warp covers 1024B contiguous, fully coalesced).
    F8 v0 = ldg256(rp + 8u * l);
    F8 v1 = ldg256(rp + 256u + 8u * l);

    s_out[l * 9u + w]          = window_mode(v0);
    s_out[(32u + l) * 9u + w]  = window_mode(v1);
    __syncthreads();

    // Store phase: thread t -> (j = t>>3 (+32r), b_off = t&7); warp STG.32s hit
    // 4 lines with full 32B sectors (bg*8 floats = 32B aligned).
    float* ob = out + (size_t)c * (NJ * B) + (size_t)(jt * JT) * B + (size_t)bg * RT;
    unsigned bo = threadIdx.x & 7u;
    unsigned j0 = threadIdx.x >> 3;          // 0..31
#pragma unroll
    for (int r = 0; r < 2; r++) {
        unsigned j = j0 + 32u * r;
        __stcs(&ob[(size_t)j * B + bo], s_out[j * 9u + bo]);
    }
}

extern "C" void kernel_launch(void* const* d_in, const int* in_sizes, int n_in,
                              void* d_out, int out_size)
{
    const float* x = (const float*)d_in[0];
    float* out = (float*)d_out;
    // blocks = 128 j-tiles * 8 b-groups * 10 c = 10240
    mode_pool_kernel<<<10240, 256>>>(x, out);
}

// round 16
// speedup vs baseline: 1.0087x; 1.0010x over previous
#include <cuda_runtime.h>
#include <cstdint>

// AdjustableModePooling — FINAL (best measured 33.248us wall, device ~30.4-31.1us,
// DRAM ~74% / 5.8-5.9 TB/s, L1 28%, rel_err 0.0; reproduced 4x on this source).
//
//   x: (64, 65536, 10) f32 of integer labels 0..9, flat-viewed as (B=64, C=10, D=65536)
//   window K1=8 along D, mode per window (ties -> smallest value)
//   out flat index = c*(8192*64) + j*64 + b
//
// Design (each element evidence-backed across 15 rounds):
//  - LDG.256 (Blackwell ld.global.nc.v8.f32): lane l loads window l WHOLE while
//    the warp covers 1024B fully coalesced (halves LDG count; L1 41->28%)
//  - lane = window along D (R3: the decisive win, -24% dur vs b-strided lanes)
//  - smem transpose (stride-9, conflict-free) -> stores 32B-full-sector coalesced
//  - nibble histogram in a u64 via fma(f,4,2^23): bits&63 == 4v, no F2I
//  - key argmax (cnt<<4)|(15-v), byte-packed + __vmaxu4 fold; tie -> smallest value
//  - int->float result via exponent-magic FADD, no I2F
//  - __stcs streaming stores (zero-reuse output)
// Measured-neutral/negative and rejected: occupancy boost (R4), cp.async pipeline
// (R6, -43%), persistent CTAs (R7, -7%), STG.64 (R8), shfl-butterfly loads (R9),
// 512-thread CTAs (R14). Kernel sits at the byte floor x achievable HBM sustain
// (~180MB mandatory traffic at ~5.9 TB/s) for this streaming access mix.

static constexpr unsigned B  = 64;
static constexpr unsigned C  = 10;
static constexpr unsigned D  = 65536;
static constexpr unsigned NJ = 8192;     // (D-8)/8+1
static constexpr unsigned JT = 64;       // windows per block tile (per row)
static constexpr unsigned RT = 8;        // rows (b values) per block = warps per block

__device__ __forceinline__ unsigned kmax(unsigned a, unsigned b) { return a > b ? a : b; }

struct F8 { float a,b,c,d,e,f,g,h; };

__device__ __forceinline__ F8 ldg256(const float* p)
{
    F8 r;
    asm volatile("ld.global.nc.v8.f32 {%0,%1,%2,%3,%4,%5,%6,%7}, [%8];"
                 : "=f"(r.a), "=f"(r.b), "=f"(r.c), "=f"(r.d),
                   "=f"(r.e), "=f"(r.f), "=f"(r.g), "=f"(r.h)
                 : "l"(p));
    return r;
}

__device__ __forceinline__ unsigned long long hist4(float a, float b_, float c_, float d_)
{
    // fma(f,4,2^23): bits = 0x4B000000 | 4v (exact for v in 0..9); bits&63 == 4v
    unsigned long long h = 0ull;
    h += 1ull << (__float_as_uint(__fmaf_rn(a,  4.0f, 8388608.0f)) & 63u);
    h += 1ull << (__float_as_uint(__fmaf_rn(b_, 4.0f, 8388608.0f)) & 63u);
    h += 1ull << (__float_as_uint(__fmaf_rn(c_, 4.0f, 8388608.0f)) & 63u);
    h += 1ull << (__float_as_uint(__fmaf_rn(d_, 4.0f, 8388608.0f)) & 63u);
    return h;
}

__device__ __forceinline__ float window_mode(const F8& v)
{
    unsigned long long acc = hist4(v.a, v.b, v.c, v.d)
                           + hist4(v.e, v.f, v.g, v.h);
    unsigned lo = (unsigned)acc;          // counts of v=0..7, nibble v
    unsigned hi = (unsigned)(acc >> 32);  // counts of v=8 (nib0), v=9 (nib1)

    // key_v = (count_v << 4) | (15 - v); max key wins; tie -> smallest v.
    unsigned E = ((lo << 4) & 0xF0F0F0F0u) | 0x090B0D0Fu;  // bytes: v=0,2,4,6
    unsigned O = ( lo       & 0xF0F0F0F0u) | 0x080A0C0Eu;  // bytes: v=1,3,5,7

    unsigned M = __vmaxu4(E, O);
    M = __vmaxu4(M, M >> 16);
    M = __vmaxu4(M, M >> 8);              // byte0 = max of the 8 low-bin keys

    unsigned k8 = ((hi << 4) & 0xF0u) | 7u;
    unsigned k9 = ( hi       & 0xF0u) | 6u;
    unsigned best = kmax(M & 0xFFu, kmax(k8, k9));

    // mode = 15 - (best & 15) = (~best) & 15 ; int->float via exponent magic
    unsigned r = (~best) & 15u;
    return __uint_as_float(0x4B000000u | r) - 8388608.0f;
}

__global__ __launch_bounds__(256, 7)
void mode_pool_kernel(const float* __restrict__ x, float* __restrict__ out)
{
    __shared__ float s_out[JT * 9];          // [j_local][row], stride 9 -> no bank conflicts

    unsigned g  = blockIdx.x;
    unsigned jt = g & 127u;                  // 128 j-tiles of 64 windows
    unsigned bg = (g >> 7) & 7u;             // 8 groups of 8 b-rows
    unsigned c  = g >> 10;                   // 0..9

    unsigned w = threadIdx.x >> 5;           // warp -> row within group
    unsigned l = threadIdx.x & 31u;          // lane -> window within 32-window chunk
    unsigned b = bg * RT + w;

    const float* rp = x + (size_t)b * (C * D) + (size_t)c * D + (size_t)jt * (JT * 8u);

    // 2 chunks of 32 windows; lane l owns window l of each chunk, loaded whole
    // as one LDG.256 (warp covers 1024B contiguous, fully coalesced).
    F8 v0 = ldg256(rp + 8u * l);
    F8 v1 = ldg256(rp + 256u + 8u * l);

    s_out[l * 9u + w]          = window_mode(v0);
    s_out[(32u + l) * 9u + w]  = window_mode(v1);
    __syncthreads();

    // Store phase: thread t -> (j = t>>3 (+32r), b_off = t&7); warp STG.32s hit
    // 4 lines with full 32B sectors (bg*8 floats = 32B aligned).
    float* ob = out + (size_t)c * (NJ * B) + (size_t)(jt * JT) * B + (size_t)bg * RT;
    unsigned bo = threadIdx.x & 7u;
    unsigned j0 = threadIdx.x >> 3;          // 0..31
#pragma unroll
    for (int r = 0; r < 2; r++) {
        unsigned j = j0 + 32u * r;
        __stcs(&ob[(size_t)j * B + bo], s_out[j * 9u + bo]);
    }
}

extern "C" void kernel_launch(void* const* d_in, const int* in_sizes, int n_in,
                              void* d_out, int out_size)
{
    const float* x = (const float*)d_in[0];
    float* out = (float*)d_out;
    // blocks = 128 j-tiles * 8 b-groups * 10 c = 10240
    mode_pool_kernel<<<10240, 256>>>(x, out);
}